// round 1
// baseline (speedup 1.0000x reference)
#include <cuda_runtime.h>
#include <cstddef>

#define Bv 16
#define Tv 576
#define NHv 12
#define HDv 64
#define DMv 768
#define LDv 256

// ---------------- scratch (static device allocations; no cudaMalloc) ---------
__device__ float g_q[Bv * Tv * DMv];     // (B*T, 768)
__device__ float g_lat[Bv * Tv * LDv];   // (B*T, 256)
__device__ float g_lp2[Bv * 144 * LDv];  // pooled s=2
__device__ float g_lp4[Bv * 36 * LDv];   // pooled s=4
__device__ float g_k[Bv * Tv * DMv];     // reused per scale
__device__ float g_v[Bv * Tv * DMv];     // reused per scale
__device__ float g_ctx[Bv * Tv * DMv];   // attention output accumulator

// ---------------- zero fill ---------------------------------------------------
__global__ void zero_kernel(float* __restrict__ p, int n) {
    int i = blockIdx.x * blockDim.x + threadIdx.x;
    int stride = gridDim.x * blockDim.x;
    for (; i < n; i += stride) p[i] = 0.f;
}

// ---------------- generic tiled GEMM: C = A(MxK) * B(KxN) (+bias) -------------
// 128x128 tile, BK=16, 256 threads, 8x8 microtile per thread.
__global__ __launch_bounds__(256) void gemm_kernel(
    const float* __restrict__ A, const float* __restrict__ B,
    const float* __restrict__ bias, float* __restrict__ C,
    int M, int N, int K) {
    __shared__ float Ast[16][132];  // transposed: Ast[kk][row]
    __shared__ float Bs[16][132];   // Bs[kk][col]

    const int bm = blockIdx.y * 128;
    const int bn = blockIdx.x * 128;
    const int tid = threadIdx.x;
    const int ty = tid >> 4;   // 0..15
    const int tx = tid & 15;   // 0..15

    float acc[8][8];
#pragma unroll
    for (int i = 0; i < 8; i++)
#pragma unroll
        for (int j = 0; j < 8; j++) acc[i][j] = 0.f;

    for (int k0 = 0; k0 < K; k0 += 16) {
        // load A tile (128x16) as float4, store transposed
#pragma unroll
        for (int u = 0; u < 2; u++) {
            int idx = u * 256 + tid;       // 0..511 float4 units
            int r = idx >> 2;              // 0..127
            int c4 = (idx & 3) << 2;       // 0,4,8,12
            float4 v = make_float4(0.f, 0.f, 0.f, 0.f);
            int row = bm + r;
            if (row < M)
                v = *(const float4*)(A + (size_t)row * K + k0 + c4);
            Ast[c4 + 0][r] = v.x;
            Ast[c4 + 1][r] = v.y;
            Ast[c4 + 2][r] = v.z;
            Ast[c4 + 3][r] = v.w;
        }
        // load B tile (16x128) as float4
#pragma unroll
        for (int u = 0; u < 2; u++) {
            int idx = u * 256 + tid;
            int kk = idx >> 5;             // 0..15
            int c4 = (idx & 31) << 2;      // 0..124
            *(float4*)&Bs[kk][c4] =
                *(const float4*)(B + (size_t)(k0 + kk) * N + bn + c4);
        }
        __syncthreads();

#pragma unroll
        for (int kk = 0; kk < 16; kk++) {
            float a[8], bb[8];
            *(float4*)&a[0] = *(const float4*)&Ast[kk][ty * 8];
            *(float4*)&a[4] = *(const float4*)&Ast[kk][ty * 8 + 4];
            *(float4*)&bb[0] = *(const float4*)&Bs[kk][tx * 8];
            *(float4*)&bb[4] = *(const float4*)&Bs[kk][tx * 8 + 4];
#pragma unroll
            for (int i = 0; i < 8; i++)
#pragma unroll
                for (int j = 0; j < 8; j++) acc[i][j] += a[i] * bb[j];
        }
        __syncthreads();
    }

    float bv[8];
#pragma unroll
    for (int j = 0; j < 8; j++)
        bv[j] = bias ? bias[bn + tx * 8 + j] : 0.f;

#pragma unroll
    for (int i = 0; i < 8; i++) {
        int row = bm + ty * 8 + i;
        if (row < M) {
            float* cp = C + (size_t)row * N + bn + tx * 8;
#pragma unroll
            for (int j = 0; j < 8; j++) cp[j] = acc[i][j] + bv[j];
        }
    }
}

// ---------------- exact sxs mean pooling --------------------------------------
__global__ void pool_kernel(const float* __restrict__ lat, float* __restrict__ out,
                            int s, int g, int n) {
    int idx = blockIdx.x * blockDim.x + threadIdx.x;
    if (idx >= n) return;
    int c = idx & (LDv - 1);
    int rest = idx >> 8;
    int cell = rest % (g * g);
    int b = rest / (g * g);
    int gh = cell / g, gw = cell % g;
    float sum = 0.f;
    for (int i = 0; i < s; i++)
        for (int j = 0; j < s; j++)
            sum += lat[((size_t)(b * Tv) + (gh * s + i) * 24 + (gw * s + j)) * LDv + c];
    out[idx] = sum / (float)(s * s);
}

// ---------------- fused attention with rel-pos bias ---------------------------
// Block: 64 queries of one (b, h). 256 threads as 16x16 grid, 4x4 microtiles.
// Online softmax over kv tiles of 64. Accumulates (softmax@V)/3 into ctx.
#define QP 68  // pad for row-major tiles (float4-aligned rows)
#define KP 65  // pad for d-major (transposed) K tile (odd stride: low conflicts)

__global__ __launch_bounds__(256) void attn_kernel(
    const float* __restrict__ qbuf, const float* __restrict__ kbuf,
    const float* __restrict__ vbuf, const float* __restrict__ tbl,
    float* __restrict__ ctx, int Kt, int gw, int s) {
    extern __shared__ float sm[];
    float* Qs = sm;                 // [64][QP]  q-major
    float* Kst = Qs + 64 * QP;      // [64][KP]  d-major (transposed)
    float* Vs = Kst + 64 * KP;      // [64][QP]  k-major
    float* Ps = Vs + 64 * QP;       // [64][QP]  q-major

    const int b = blockIdx.z;
    const int h = blockIdx.y;
    const int q0 = blockIdx.x * 64;
    const int tid = threadIdx.x;
    const int ty = tid >> 4;
    const int tx = tid & 15;

    // load Q tile (coalesced float4)
    const float* qsrc = qbuf + ((size_t)(b * Tv + q0)) * DMv + h * HDv;
#pragma unroll
    for (int u = 0; u < 4; u++) {
        int idx = u * 256 + tid;
        int r = idx >> 4;
        int d4 = (idx & 15) << 2;
        *(float4*)&Qs[r * QP + d4] = *(const float4*)(qsrc + (size_t)r * DMv + d4);
    }

    float o[4][4];
#pragma unroll
    for (int i = 0; i < 4; i++)
#pragma unroll
        for (int j = 0; j < 4; j++) o[i][j] = 0.f;
    float mrow[4] = {-1e30f, -1e30f, -1e30f, -1e30f};
    float lrow[4] = {0.f, 0.f, 0.f, 0.f};

    const float scl = 0.125f;  // 1/sqrt(64)
    const int tw = 2 * gw - 1;
    const int tbl_off = h * (47 * tw);
    const float hctr = 0.5f * (float)(s - 1);

    int qh_[4], qw_[4];
#pragma unroll
    for (int i = 0; i < 4; i++) {
        int qi = q0 + 4 * ty + i;
        qh_[i] = qi / 24;
        qw_[i] = qi % 24;
    }

    const int ntiles = (Kt + 63) >> 6;
    for (int kt = 0; kt < ntiles; kt++) {
        __syncthreads();  // prior iteration done reading Kst/Vs/Ps
        // load K (transposed) and V tiles
#pragma unroll
        for (int u = 0; u < 4; u++) {
            int idx = u * 256 + tid;
            int r = idx >> 4;
            int d4 = (idx & 15) << 2;
            int kg = kt * 64 + r;
            float4 kv = make_float4(0.f, 0.f, 0.f, 0.f);
            float4 vv = make_float4(0.f, 0.f, 0.f, 0.f);
            if (kg < Kt) {
                size_t base = ((size_t)(b * Kt + kg)) * DMv + h * HDv + d4;
                kv = *(const float4*)(kbuf + base);
                vv = *(const float4*)(vbuf + base);
            }
            Kst[(d4 + 0) * KP + r] = kv.x;
            Kst[(d4 + 1) * KP + r] = kv.y;
            Kst[(d4 + 2) * KP + r] = kv.z;
            Kst[(d4 + 3) * KP + r] = kv.w;
            *(float4*)&Vs[r * QP + d4] = vv;
        }
        __syncthreads();

        // S = Q K^T
        float sc[4][4];
#pragma unroll
        for (int i = 0; i < 4; i++)
#pragma unroll
            for (int j = 0; j < 4; j++) sc[i][j] = 0.f;
#pragma unroll 16
        for (int kd = 0; kd < 64; kd++) {
            float kvv[4], qvv[4];
#pragma unroll
            for (int j = 0; j < 4; j++) kvv[j] = Kst[kd * KP + 4 * tx + j];
#pragma unroll
            for (int i = 0; i < 4; i++) qvv[i] = Qs[(4 * ty + i) * QP + kd];
#pragma unroll
            for (int i = 0; i < 4; i++)
#pragma unroll
                for (int j = 0; j < 4; j++) sc[i][j] += qvv[i] * kvv[j];
        }

        // scale + rel-pos bias + mask (replicates trunc-toward-zero & flat index)
#pragma unroll
        for (int j = 0; j < 4; j++) {
            int kg = kt * 64 + 4 * tx + j;
            bool valid = (kg < Kt);
            int kk = valid ? kg : 0;
            int khg = kk / gw, kwg = kk % gw;
            float khc = (float)(khg * s) + hctr;
            float kwc = (float)(kwg * s) + hctr;
#pragma unroll
            for (int i = 0; i < 4; i++) {
                if (valid) {
                    int rh = (int)((float)qh_[i] - khc) + 23;
                    int rw = (int)((float)qw_[i] - kwc) + (gw - 1);
                    sc[i][j] = sc[i][j] * scl + tbl[tbl_off + rh * tw + rw];
                } else {
                    sc[i][j] = -1e30f;
                }
            }
        }

        // online softmax per q-row (16 tx lanes hold one row's 64 cols)
#pragma unroll
        for (int i = 0; i < 4; i++) {
            float mx = fmaxf(fmaxf(sc[i][0], sc[i][1]), fmaxf(sc[i][2], sc[i][3]));
#pragma unroll
            for (int off = 8; off > 0; off >>= 1)
                mx = fmaxf(mx, __shfl_xor_sync(0xffffffffu, mx, off, 16));
            float mnew = fmaxf(mrow[i], mx);
            float corr = __expf(mrow[i] - mnew);
            float rs = 0.f;
#pragma unroll
            for (int j = 0; j < 4; j++) {
                float p = __expf(sc[i][j] - mnew);
                Ps[(4 * ty + i) * QP + 4 * tx + j] = p;
                rs += p;
            }
#pragma unroll
            for (int off = 8; off > 0; off >>= 1)
                rs += __shfl_xor_sync(0xffffffffu, rs, off, 16);
            lrow[i] = lrow[i] * corr + rs;
            mrow[i] = mnew;
#pragma unroll
            for (int j = 0; j < 4; j++) o[i][j] *= corr;
        }
        __syncthreads();

        // O += P @ V
#pragma unroll 16
        for (int kd = 0; kd < 64; kd++) {
            float pv[4];
#pragma unroll
            for (int i = 0; i < 4; i++) pv[i] = Ps[(4 * ty + i) * QP + kd];
            float4 vv = *(const float4*)&Vs[kd * QP + 4 * tx];
#pragma unroll
            for (int i = 0; i < 4; i++) {
                o[i][0] += pv[i] * vv.x;
                o[i][1] += pv[i] * vv.y;
                o[i][2] += pv[i] * vv.z;
                o[i][3] += pv[i] * vv.w;
            }
        }
    }

    // write: ctx += (O / l) / 3
#pragma unroll
    for (int i = 0; i < 4; i++) {
        float inv = 1.f / (3.f * lrow[i]);
        float* cp = ctx + ((size_t)(b * Tv + q0 + 4 * ty + i)) * DMv + h * HDv + 4 * tx;
#pragma unroll
        for (int j = 0; j < 4; j++) cp[j] += o[i][j] * inv;
    }
}

// ---------------- launch ------------------------------------------------------
extern "C" void kernel_launch(void* const* d_in, const int* in_sizes, int n_in,
                              void* d_out, int out_size) {
    const float* x    = (const float*)d_in[0];
    const float* wq   = (const float*)d_in[1];
    const float* wdkv = (const float*)d_in[2];
    const float* wuk1 = (const float*)d_in[3];
    const float* wuk2 = (const float*)d_in[4];
    const float* wuk4 = (const float*)d_in[5];
    const float* wuv1 = (const float*)d_in[6];
    const float* wuv2 = (const float*)d_in[7];
    const float* wuv4 = (const float*)d_in[8];
    const float* wout = (const float*)d_in[9];
    const float* bout = (const float*)d_in[10];
    const float* tbl1 = (const float*)d_in[11];
    const float* tbl2 = (const float*)d_in[12];
    const float* tbl4 = (const float*)d_in[13];

    float *q, *lat, *lp2, *lp4, *k, *v, *ctx;
    cudaGetSymbolAddress((void**)&q, g_q);
    cudaGetSymbolAddress((void**)&lat, g_lat);
    cudaGetSymbolAddress((void**)&lp2, g_lp2);
    cudaGetSymbolAddress((void**)&lp4, g_lp4);
    cudaGetSymbolAddress((void**)&k, g_k);
    cudaGetSymbolAddress((void**)&v, g_v);
    cudaGetSymbolAddress((void**)&ctx, g_ctx);

    const int ATT_SMEM = (64 * QP * 3 + 64 * KP) * 4;  // 68,864 B
    cudaFuncSetAttribute(attn_kernel, cudaFuncAttributeMaxDynamicSharedMemorySize,
                         ATT_SMEM);

    const int MQ = Bv * Tv;  // 9216

    zero_kernel<<<1024, 256>>>(ctx, MQ * DMv);

    gemm_kernel<<<dim3(6, 72), 256>>>(x, wq, nullptr, q, MQ, DMv, DMv);
    gemm_kernel<<<dim3(2, 72), 256>>>(x, wdkv, nullptr, lat, MQ, LDv, DMv);

    // ---- scale 1 (K = 576) ----
    gemm_kernel<<<dim3(6, 72), 256>>>(lat, wuk1, nullptr, k, MQ, DMv, LDv);
    gemm_kernel<<<dim3(6, 72), 256>>>(lat, wuv1, nullptr, v, MQ, DMv, LDv);
    attn_kernel<<<dim3(9, NHv, Bv), 256, ATT_SMEM>>>(q, k, v, tbl1, ctx, 576, 24, 1);

    // ---- scale 2 (K = 144) ----
    pool_kernel<<<(Bv * 144 * LDv + 255) / 256, 256>>>(lat, lp2, 2, 12, Bv * 144 * LDv);
    gemm_kernel<<<dim3(6, 18), 256>>>(lp2, wuk2, nullptr, k, Bv * 144, DMv, LDv);
    gemm_kernel<<<dim3(6, 18), 256>>>(lp2, wuv2, nullptr, v, Bv * 144, DMv, LDv);
    attn_kernel<<<dim3(9, NHv, Bv), 256, ATT_SMEM>>>(q, k, v, tbl2, ctx, 144, 12, 2);

    // ---- scale 4 (K = 36) ----
    pool_kernel<<<(Bv * 36 * LDv + 255) / 256, 256>>>(lat, lp4, 4, 6, Bv * 36 * LDv);
    gemm_kernel<<<dim3(6, 5), 256>>>(lp4, wuk4, nullptr, k, Bv * 36, DMv, LDv);
    gemm_kernel<<<dim3(6, 5), 256>>>(lp4, wuv4, nullptr, v, Bv * 36, DMv, LDv);
    attn_kernel<<<dim3(9, NHv, Bv), 256, ATT_SMEM>>>(q, k, v, tbl4, ctx, 36, 6, 4);

    // ---- output projection ----
    gemm_kernel<<<dim3(6, 72), 256>>>(ctx, wout, bout, (float*)d_out, MQ, DMv, DMv);
}

// round 2
// speedup vs baseline: 2.3344x; 2.3344x over previous
#include <cuda_runtime.h>
#include <cstdint>
#include <cstddef>

#define Bv 16
#define Tv 576
#define NHv 12
#define HDv 64
#define DMv 768
#define LDv 256

// ---------------- scratch (static device allocations; no cudaMalloc) ---------
__device__ float g_q[Bv * Tv * DMv];
__device__ float g_lat[Bv * Tv * LDv];
__device__ float g_lp2[Bv * 144 * LDv];
__device__ float g_lp4[Bv * 36 * LDv];
__device__ float g_k[Bv * Tv * DMv];
__device__ float g_v[Bv * Tv * DMv];
__device__ float g_ctx[Bv * Tv * DMv];

// ---------------- helpers -----------------------------------------------------
__device__ __forceinline__ uint32_t f2tf(float f) {
    uint32_t u;
    asm("cvt.rna.tf32.f32 %0, %1;" : "=r"(u) : "f"(f));
    return u;
}

__device__ __forceinline__ void mma_tf32(float& c0, float& c1, float& c2, float& c3,
                                         uint32_t a0, uint32_t a1, uint32_t a2, uint32_t a3,
                                         uint32_t b0, uint32_t b1) {
    asm volatile(
        "mma.sync.aligned.m16n8k8.row.col.f32.tf32.tf32.f32 "
        "{%0,%1,%2,%3}, {%4,%5,%6,%7}, {%8,%9}, {%0,%1,%2,%3};"
        : "+f"(c0), "+f"(c1), "+f"(c2), "+f"(c3)
        : "r"(a0), "r"(a1), "r"(a2), "r"(a3), "r"(b0), "r"(b1));
}

// ---------------- zero fill ---------------------------------------------------
__global__ void zero_kernel(float* __restrict__ p, int n) {
    int i = blockIdx.x * blockDim.x + threadIdx.x;
    int stride = gridDim.x * blockDim.x;
    for (; i < n; i += stride) p[i] = 0.f;
}

// ---------------- tf32 tensor-core GEMM: C = A(MxK) B(KxN) (+bias) ------------
// 128x128 tile, BK=32, 256 threads (8 warps, 2x4), warp tile 64x32.
__global__ __launch_bounds__(256) void gemm_tc(
    const float* __restrict__ A, const float* __restrict__ B,
    const float* __restrict__ bias, float* __restrict__ C,
    int M, int N, int K) {
    __shared__ uint32_t As[128 * 36];  // [m][k] stride 36
    __shared__ uint32_t Bs[32 * 132];  // [k][n] stride 132

    const int bm = blockIdx.y * 128;
    const int bn = blockIdx.x * 128;
    const int tid = threadIdx.x;
    const int lane = tid & 31;
    const int warp = tid >> 5;
    const int wm = (warp & 1) * 64;
    const int wn = (warp >> 1) * 32;
    const int g = lane >> 2;
    const int t = lane & 3;

    float c[4][4][4];
#pragma unroll
    for (int mt = 0; mt < 4; mt++)
#pragma unroll
        for (int nt = 0; nt < 4; nt++)
#pragma unroll
            for (int r = 0; r < 4; r++) c[mt][nt][r] = 0.f;

    for (int k0 = 0; k0 < K; k0 += 32) {
        // A tile: 128x32
#pragma unroll
        for (int u = 0; u < 4; u++) {
            int idx = u * 256 + tid;
            int r = idx >> 3;
            int c4 = (idx & 7) << 2;
            float4 v = make_float4(0.f, 0.f, 0.f, 0.f);
            if (bm + r < M)
                v = *(const float4*)(A + (size_t)(bm + r) * K + k0 + c4);
            uint32_t* dst = &As[r * 36 + c4];
            dst[0] = f2tf(v.x); dst[1] = f2tf(v.y);
            dst[2] = f2tf(v.z); dst[3] = f2tf(v.w);
        }
        // B tile: 32x128
#pragma unroll
        for (int u = 0; u < 4; u++) {
            int idx = u * 256 + tid;
            int kk = idx >> 5;
            int c4 = (idx & 31) << 2;
            float4 v = *(const float4*)(B + (size_t)(k0 + kk) * N + bn + c4);
            uint32_t* dst = &Bs[kk * 132 + c4];
            dst[0] = f2tf(v.x); dst[1] = f2tf(v.y);
            dst[2] = f2tf(v.z); dst[3] = f2tf(v.w);
        }
        __syncthreads();

#pragma unroll
        for (int ks = 0; ks < 4; ks++) {
            uint32_t af[4][4], bf[4][2];
#pragma unroll
            for (int mt = 0; mt < 4; mt++) {
                int r = wm + mt * 16 + g;
                af[mt][0] = As[r * 36 + ks * 8 + t];
                af[mt][1] = As[(r + 8) * 36 + ks * 8 + t];
                af[mt][2] = As[r * 36 + ks * 8 + t + 4];
                af[mt][3] = As[(r + 8) * 36 + ks * 8 + t + 4];
            }
#pragma unroll
            for (int nt = 0; nt < 4; nt++) {
                int col = wn + nt * 8 + g;
                bf[nt][0] = Bs[(ks * 8 + t) * 132 + col];
                bf[nt][1] = Bs[(ks * 8 + t + 4) * 132 + col];
            }
#pragma unroll
            for (int mt = 0; mt < 4; mt++)
#pragma unroll
                for (int nt = 0; nt < 4; nt++)
                    mma_tf32(c[mt][nt][0], c[mt][nt][1], c[mt][nt][2], c[mt][nt][3],
                             af[mt][0], af[mt][1], af[mt][2], af[mt][3],
                             bf[nt][0], bf[nt][1]);
        }
        __syncthreads();
    }

#pragma unroll
    for (int mt = 0; mt < 4; mt++) {
#pragma unroll
        for (int nt = 0; nt < 4; nt++) {
            int row0 = bm + wm + mt * 16 + g;
            int col = bn + wn + nt * 8 + t * 2;
            float b0 = bias ? bias[col] : 0.f;
            float b1 = bias ? bias[col + 1] : 0.f;
            if (row0 < M) {
                float2 v = make_float2(c[mt][nt][0] + b0, c[mt][nt][1] + b1);
                *(float2*)(C + (size_t)row0 * N + col) = v;
            }
            if (row0 + 8 < M) {
                float2 v = make_float2(c[mt][nt][2] + b0, c[mt][nt][3] + b1);
                *(float2*)(C + (size_t)(row0 + 8) * N + col) = v;
            }
        }
    }
}

// ---------------- exact sxs mean pooling --------------------------------------
__global__ void pool_kernel(const float* __restrict__ lat, float* __restrict__ out,
                            int s, int g, int n) {
    int idx = blockIdx.x * blockDim.x + threadIdx.x;
    if (idx >= n) return;
    int c = idx & (LDv - 1);
    int rest = idx >> 8;
    int cell = rest % (g * g);
    int b = rest / (g * g);
    int gh = cell / g, gw = cell % g;
    float sum = 0.f;
    for (int i = 0; i < s; i++)
        for (int j = 0; j < s; j++)
            sum += lat[((size_t)(b * Tv) + (gh * s + i) * 24 + (gw * s + j)) * LDv + c];
    out[idx] = sum / (float)(s * s);
}

// ---------------- tensor-core flash attention with rel-pos bias ----------------
// Block: 64 queries of one (b,h). 128 threads = 4 warps; warp w owns q rows
// [w*16, w*16+16) and all 64 keys of a tile. Online softmax in registers,
// P staged to smem as tf32 for the PV mma. Accumulates (softmax@V)/3 into ctx.
#define DP 68  // smem row stride (uint32 units)

__global__ __launch_bounds__(128) void attn_tc(
    const float* __restrict__ qbuf, const float* __restrict__ kbuf,
    const float* __restrict__ vbuf, const float* __restrict__ tbl,
    float* __restrict__ ctx, int Kt, int gw, int s) {
    extern __shared__ uint32_t smu[];
    uint32_t* Qs = smu;               // [64][DP] tf32, q-major
    uint32_t* Ks = Qs + 64 * DP;      // [64][DP] tf32, k-major
    uint32_t* Vs = Ks + 64 * DP;      // [64][DP] tf32, k-major
    uint32_t* Ps = Vs + 64 * DP;      // [64][DP] tf32, q-major (cols = keys)
    float* khcs = (float*)(Ps + 64 * DP);  // [64]
    float* kwcs = khcs + 64;               // [64]

    const int b = blockIdx.z;
    const int h = blockIdx.y;
    const int q0 = blockIdx.x * 64;
    const int tid = threadIdx.x;
    const int lane = tid & 31;
    const int w = tid >> 5;
    const int g = lane >> 2;
    const int t = lane & 3;

    const int lr0 = w * 16 + g;      // local q row of c0/c1
    const int lr1 = lr0 + 8;         // local q row of c2/c3

    // load Q tile (64 x 64), cvt to tf32
    const float* qsrc = qbuf + ((size_t)(b * Tv + q0)) * DMv + h * HDv;
#pragma unroll
    for (int u = 0; u < 8; u++) {
        int idx = u * 128 + tid;
        int r = idx >> 4;
        int c4 = (idx & 15) << 2;
        float4 v = *(const float4*)(qsrc + (size_t)r * DMv + c4);
        uint32_t* dst = &Qs[r * DP + c4];
        dst[0] = f2tf(v.x); dst[1] = f2tf(v.y);
        dst[2] = f2tf(v.z); dst[3] = f2tf(v.w);
    }

    float o[8][4];
#pragma unroll
    for (int nt = 0; nt < 8; nt++)
#pragma unroll
        for (int r = 0; r < 4; r++) o[nt][r] = 0.f;
    float m0 = -1e30f, m1 = -1e30f, l0 = 0.f, l1 = 0.f;

    const float scl = 0.125f;
    const int tw = 2 * gw - 1;
    const int tbl_off = h * (47 * tw);
    const float hctr = 0.5f * (float)(s - 1);

    const int qi0 = q0 + lr0;
    const int qi1 = q0 + lr1;
    const float qh0 = (float)(qi0 / 24), qw0 = (float)(qi0 % 24);
    const float qh1 = (float)(qi1 / 24), qw1 = (float)(qi1 % 24);

    const int ntiles = (Kt + 63) >> 6;
    for (int kt = 0; kt < ntiles; kt++) {
        __syncthreads();  // previous PV done reading Ks/Vs
        // load K/V tile (64 x 64 each) + key centers
#pragma unroll
        for (int u = 0; u < 8; u++) {
            int idx = u * 128 + tid;
            int r = idx >> 4;
            int c4 = (idx & 15) << 2;
            int kg = kt * 64 + r;
            float4 kv = make_float4(0.f, 0.f, 0.f, 0.f);
            float4 vv = make_float4(0.f, 0.f, 0.f, 0.f);
            if (kg < Kt) {
                size_t base = ((size_t)(b * Kt + kg)) * DMv + h * HDv + c4;
                kv = *(const float4*)(kbuf + base);
                vv = *(const float4*)(vbuf + base);
            }
            uint32_t* dk = &Ks[r * DP + c4];
            dk[0] = f2tf(kv.x); dk[1] = f2tf(kv.y);
            dk[2] = f2tf(kv.z); dk[3] = f2tf(kv.w);
            uint32_t* dv = &Vs[r * DP + c4];
            dv[0] = f2tf(vv.x); dv[1] = f2tf(vv.y);
            dv[2] = f2tf(vv.z); dv[3] = f2tf(vv.w);
        }
        if (tid < 64) {
            int kg = kt * 64 + tid;
            if (kg < Kt) {
                int khg = kg / gw, kwg = kg % gw;
                khcs[tid] = (float)(khg * s) + hctr;
                kwcs[tid] = (float)(kwg * s) + hctr;
            }
        }
        __syncthreads();

        // ---- S = Q K^T (m16 x n8 x k8, 8 n-tiles, 8 k-steps) ----
        float sf[8][4];
#pragma unroll
        for (int nt = 0; nt < 8; nt++)
#pragma unroll
            for (int r = 0; r < 4; r++) sf[nt][r] = 0.f;
#pragma unroll
        for (int kd = 0; kd < 8; kd++) {
            uint32_t a0 = Qs[lr0 * DP + kd * 8 + t];
            uint32_t a1 = Qs[lr1 * DP + kd * 8 + t];
            uint32_t a2 = Qs[lr0 * DP + kd * 8 + t + 4];
            uint32_t a3 = Qs[lr1 * DP + kd * 8 + t + 4];
#pragma unroll
            for (int nt = 0; nt < 8; nt++) {
                uint32_t b0 = Ks[(nt * 8 + g) * DP + kd * 8 + t];
                uint32_t b1 = Ks[(nt * 8 + g) * DP + kd * 8 + t + 4];
                mma_tf32(sf[nt][0], sf[nt][1], sf[nt][2], sf[nt][3],
                         a0, a1, a2, a3, b0, b1);
            }
        }

        // ---- scale + bias + mask ----
#pragma unroll
        for (int nt = 0; nt < 8; nt++) {
#pragma unroll
            for (int cc = 0; cc < 2; cc++) {
                int lc = nt * 8 + t * 2 + cc;   // local key col
                int kg = kt * 64 + lc;
                if (kg < Kt) {
                    float khc = khcs[lc], kwc = kwcs[lc];
                    int rh0 = (int)(qh0 - khc) + 23;
                    int rw0 = (int)(qw0 - kwc) + (gw - 1);
                    int rh1 = (int)(qh1 - khc) + 23;
                    int rw1 = (int)(qw1 - kwc) + (gw - 1);
                    sf[nt][cc]     = sf[nt][cc] * scl + __ldg(&tbl[tbl_off + rh0 * tw + rw0]);
                    sf[nt][cc + 2] = sf[nt][cc + 2] * scl + __ldg(&tbl[tbl_off + rh1 * tw + rw1]);
                } else {
                    sf[nt][cc] = -1e30f;
                    sf[nt][cc + 2] = -1e30f;
                }
            }
        }

        // ---- online softmax (rows live in quads: xor 1, xor 2) ----
        float mx0 = -1e30f, mx1 = -1e30f;
#pragma unroll
        for (int nt = 0; nt < 8; nt++) {
            mx0 = fmaxf(mx0, fmaxf(sf[nt][0], sf[nt][1]));
            mx1 = fmaxf(mx1, fmaxf(sf[nt][2], sf[nt][3]));
        }
        mx0 = fmaxf(mx0, __shfl_xor_sync(0xffffffffu, mx0, 1));
        mx0 = fmaxf(mx0, __shfl_xor_sync(0xffffffffu, mx0, 2));
        mx1 = fmaxf(mx1, __shfl_xor_sync(0xffffffffu, mx1, 1));
        mx1 = fmaxf(mx1, __shfl_xor_sync(0xffffffffu, mx1, 2));
        float mn0 = fmaxf(m0, mx0), mn1 = fmaxf(m1, mx1);
        float cr0 = __expf(m0 - mn0), cr1 = __expf(m1 - mn1);
        float rs0 = 0.f, rs1 = 0.f;
#pragma unroll
        for (int nt = 0; nt < 8; nt++) {
            float p0 = __expf(sf[nt][0] - mn0);
            float p1 = __expf(sf[nt][1] - mn0);
            float p2 = __expf(sf[nt][2] - mn1);
            float p3 = __expf(sf[nt][3] - mn1);
            rs0 += p0 + p1;
            rs1 += p2 + p3;
            int col = nt * 8 + t * 2;
            Ps[lr0 * DP + col] = f2tf(p0);
            Ps[lr0 * DP + col + 1] = f2tf(p1);
            Ps[lr1 * DP + col] = f2tf(p2);
            Ps[lr1 * DP + col + 1] = f2tf(p3);
        }
        rs0 += __shfl_xor_sync(0xffffffffu, rs0, 1);
        rs0 += __shfl_xor_sync(0xffffffffu, rs0, 2);
        rs1 += __shfl_xor_sync(0xffffffffu, rs1, 1);
        rs1 += __shfl_xor_sync(0xffffffffu, rs1, 2);
        l0 = l0 * cr0 + rs0;
        l1 = l1 * cr1 + rs1;
        m0 = mn0;
        m1 = mn1;
#pragma unroll
        for (int nt = 0; nt < 8; nt++) {
            o[nt][0] *= cr0; o[nt][1] *= cr0;
            o[nt][2] *= cr1; o[nt][3] *= cr1;
        }
        __syncwarp();

        // ---- O += P V (m16 x n8(d) x k8(keys), 8 n-tiles, 8 k-steps) ----
#pragma unroll
        for (int ks = 0; ks < 8; ks++) {
            uint32_t a0 = Ps[lr0 * DP + ks * 8 + t];
            uint32_t a1 = Ps[lr1 * DP + ks * 8 + t];
            uint32_t a2 = Ps[lr0 * DP + ks * 8 + t + 4];
            uint32_t a3 = Ps[lr1 * DP + ks * 8 + t + 4];
#pragma unroll
            for (int nt = 0; nt < 8; nt++) {
                uint32_t b0 = Vs[(ks * 8 + t) * DP + nt * 8 + g];
                uint32_t b1 = Vs[(ks * 8 + t + 4) * DP + nt * 8 + g];
                mma_tf32(o[nt][0], o[nt][1], o[nt][2], o[nt][3],
                         a0, a1, a2, a3, b0, b1);
            }
        }
    }

    // ---- write: ctx += (O / l) / 3 ----
    float inv0 = 1.f / (3.f * l0);
    float inv1 = 1.f / (3.f * l1);
    float* c0p = ctx + ((size_t)(b * Tv + q0 + lr0)) * DMv + h * HDv;
    float* c1p = ctx + ((size_t)(b * Tv + q0 + lr1)) * DMv + h * HDv;
#pragma unroll
    for (int nt = 0; nt < 8; nt++) {
        int col = nt * 8 + t * 2;
        c0p[col] += o[nt][0] * inv0;
        c0p[col + 1] += o[nt][1] * inv0;
        c1p[col] += o[nt][2] * inv1;
        c1p[col + 1] += o[nt][3] * inv1;
    }
}

// ---------------- launch ------------------------------------------------------
extern "C" void kernel_launch(void* const* d_in, const int* in_sizes, int n_in,
                              void* d_out, int out_size) {
    const float* x    = (const float*)d_in[0];
    const float* wq   = (const float*)d_in[1];
    const float* wdkv = (const float*)d_in[2];
    const float* wuk1 = (const float*)d_in[3];
    const float* wuk2 = (const float*)d_in[4];
    const float* wuk4 = (const float*)d_in[5];
    const float* wuv1 = (const float*)d_in[6];
    const float* wuv2 = (const float*)d_in[7];
    const float* wuv4 = (const float*)d_in[8];
    const float* wout = (const float*)d_in[9];
    const float* bout = (const float*)d_in[10];
    const float* tbl1 = (const float*)d_in[11];
    const float* tbl2 = (const float*)d_in[12];
    const float* tbl4 = (const float*)d_in[13];

    float *q, *lat, *lp2, *lp4, *k, *v, *ctx;
    cudaGetSymbolAddress((void**)&q, g_q);
    cudaGetSymbolAddress((void**)&lat, g_lat);
    cudaGetSymbolAddress((void**)&lp2, g_lp2);
    cudaGetSymbolAddress((void**)&lp4, g_lp4);
    cudaGetSymbolAddress((void**)&k, g_k);
    cudaGetSymbolAddress((void**)&v, g_v);
    cudaGetSymbolAddress((void**)&ctx, g_ctx);

    const int ATT_SMEM = (4 * 64 * DP) * 4 + 2 * 64 * 4;  // ~70 KB
    cudaFuncSetAttribute(attn_tc, cudaFuncAttributeMaxDynamicSharedMemorySize,
                         ATT_SMEM);

    const int MQ = Bv * Tv;  // 9216

    zero_kernel<<<1024, 256>>>(ctx, MQ * DMv);

    gemm_tc<<<dim3(6, 72), 256>>>(x, wq, nullptr, q, MQ, DMv, DMv);
    gemm_tc<<<dim3(2, 72), 256>>>(x, wdkv, nullptr, lat, MQ, LDv, DMv);

    // ---- scale 1 (K = 576) ----
    gemm_tc<<<dim3(6, 72), 256>>>(lat, wuk1, nullptr, k, MQ, DMv, LDv);
    gemm_tc<<<dim3(6, 72), 256>>>(lat, wuv1, nullptr, v, MQ, DMv, LDv);
    attn_tc<<<dim3(9, NHv, Bv), 128, ATT_SMEM>>>(q, k, v, tbl1, ctx, 576, 24, 1);

    // ---- scale 2 (K = 144) ----
    pool_kernel<<<(Bv * 144 * LDv + 255) / 256, 256>>>(lat, lp2, 2, 12, Bv * 144 * LDv);
    gemm_tc<<<dim3(6, 18), 256>>>(lp2, wuk2, nullptr, k, Bv * 144, DMv, LDv);
    gemm_tc<<<dim3(6, 18), 256>>>(lp2, wuv2, nullptr, v, Bv * 144, DMv, LDv);
    attn_tc<<<dim3(9, NHv, Bv), 128, ATT_SMEM>>>(q, k, v, tbl2, ctx, 144, 12, 2);

    // ---- scale 4 (K = 36) ----
    pool_kernel<<<(Bv * 36 * LDv + 255) / 256, 256>>>(lat, lp4, 4, 6, Bv * 36 * LDv);
    gemm_tc<<<dim3(6, 5), 256>>>(lp4, wuk4, nullptr, k, Bv * 36, DMv, LDv);
    gemm_tc<<<dim3(6, 5), 256>>>(lp4, wuv4, nullptr, v, Bv * 36, DMv, LDv);
    attn_tc<<<dim3(9, NHv, Bv), 128, ATT_SMEM>>>(q, k, v, tbl4, ctx, 36, 6, 4);

    // ---- output projection ----
    gemm_tc<<<dim3(6, 72), 256>>>(ctx, wout, bout, (float*)d_out, MQ, DMv, DMv);
}